// round 11
// baseline (speedup 1.0000x reference)
#include <cuda_runtime.h>
#include <cuda_fp16.h>
#include <cstdint>

// Problem constants: N=100000, D=64, H=4, DK=16, E=1600000
#define MAXN 100000
#define MAXE 1600000

// xt = C1*x + C2*(x @ W^T)  where M^4, M=[[1,.25],[-.25,1]] (exact binary fracs)
#define C1 0.62890625f
#define C2 0.9375f
#define KI 1.56640625f   // C1 + C2 (exact), used when W == I
#define ALPHA 0.2f

// Scratch (static device arrays — no allocation allowed)
__device__ __half g_xth[MAXN * 64];   // transformed features, fp16 (12.8 MB)
__device__ float4 g_ssrc[MAXN];       // per-node per-head src score
__device__ float4 g_sdst[MAXN];       // per-node per-head dst score
__device__ float4 g_denom[MAXN];      // softmax denominator accumulators
__device__ float4 g_di[MAXN];         // 0.25/(denom+eps)
__device__ int    g_cnt[MAXN];        // out-degree by row
__device__ int    g_start[MAXN];      // CSR row start
__device__ int    g_cursor[MAXN];     // fill cursor
__device__ int    g_total;            // scan running offset
__device__ int    g_wflag;            // 0 iff W == identity
__device__ float4 g_e4[MAXE];         // per-edge exps (written seq by kDenom)
__device__ float2 g_cw[MAXE];         // per-edge (col, w) in CSR order

__device__ __forceinline__ float lrelu(float v) {
    return v > 0.0f ? v : ALPHA * v;
}

// ---------------------------------------------------------------------------
// Zero per-replay state; also verify W == identity (first 4096 threads)
// ---------------------------------------------------------------------------
__global__ void kZero(const float* __restrict__ W, int n_nodes) {
    int i = blockIdx.x * blockDim.x + threadIdx.x;
    if (i == 0) { g_total = 0; g_wflag = 0; }
    if (i < 4096) {
        float expect = (i / 64 == i % 64) ? 1.0f : 0.0f;
        unsigned bad = __ballot_sync(0xffffffffu, W[i] != expect);
        if ((threadIdx.x & 31) == 0 && bad) atomicOr(&g_wflag, 1);
    }
    if (i < n_nodes) {
        g_denom[i] = make_float4(0.f, 0.f, 0.f, 0.f);
        g_cnt[i] = 0;
    }
}

// ---------------------------------------------------------------------------
// Per-node: xt = C1*x + C2*(x@W^T) (stored fp16); per-head scores (fp32).
// Fast path (W==I): xt = KI*x, pure streaming.
// ---------------------------------------------------------------------------
__global__ void __launch_bounds__(256) kNode(
    const float* __restrict__ x, const float* __restrict__ W,
    const float* __restrict__ a, int n_nodes)
{
    __shared__ float4 sW[1024];
    __shared__ float  sA[32];
    const bool ident = (g_wflag == 0);
    if (!ident) {
        for (int k = threadIdx.x; k < 1024; k += blockDim.x)
            sW[k] = ((const float4*)W)[k];
    }
    if (threadIdx.x < 32) sA[threadIdx.x] = a[threadIdx.x];
    __syncthreads();

    int n = blockIdx.x * blockDim.x + threadIdx.x;
    if (n >= n_nodes) return;

    float4 xr[16];
    const float4* xv = (const float4*)(x + (size_t)n * 64);
#pragma unroll
    for (int i = 0; i < 16; i++) xr[i] = xv[i];

    float ss[4] = {0.f, 0.f, 0.f, 0.f};
    float sd[4] = {0.f, 0.f, 0.f, 0.f};
    uint32_t hbuf[32];   // 64 halfs as 32 half2 words

    if (ident) {
#pragma unroll
        for (int jq = 0; jq < 16; jq++) {
            const int h = jq >> 2;
            float4 xq = xr[jq];
            float t0 = KI * xq.x, t1 = KI * xq.y, t2 = KI * xq.z, t3 = KI * xq.w;
            const int k = (jq & 3) * 4;
            ss[h] = fmaf(t0, sA[k],     fmaf(t1, sA[k+1],    fmaf(t2, sA[k+2],    fmaf(t3, sA[k+3],    ss[h]))));
            sd[h] = fmaf(t0, sA[16+k],  fmaf(t1, sA[16+k+1], fmaf(t2, sA[16+k+2], fmaf(t3, sA[16+k+3], sd[h]))));
            __half2 h0 = __floats2half2_rn(t0, t1);
            __half2 h1 = __floats2half2_rn(t2, t3);
            hbuf[jq * 2]     = *(uint32_t*)&h0;
            hbuf[jq * 2 + 1] = *(uint32_t*)&h1;
        }
    } else {
#pragma unroll
        for (int h = 0; h < 4; h++) {
#pragma unroll
            for (int kq = 0; kq < 4; kq++) {
                const int jq = h * 4 + kq;
                float4 xq = xr[jq];
                float t4[4];
#pragma unroll
                for (int m = 0; m < 4; m++) {
                    const int j = jq * 4 + m;
                    const float4* wr = &sW[j * 16];
                    float p = 0.f;
#pragma unroll
                    for (int i = 0; i < 16; i++) {
                        float4 w  = wr[i];
                        float4 xx = xr[i];
                        p = fmaf(xx.x, w.x, p);
                        p = fmaf(xx.y, w.y, p);
                        p = fmaf(xx.z, w.z, p);
                        p = fmaf(xx.w, w.w, p);
                    }
                    float xc = (m == 0) ? xq.x : (m == 1) ? xq.y : (m == 2) ? xq.z : xq.w;
                    float t  = fmaf(C2, p, C1 * xc);
                    const int k = kq * 4 + m;
                    ss[h] = fmaf(t, sA[k],      ss[h]);
                    sd[h] = fmaf(t, sA[16 + k], sd[h]);
                    t4[m] = t;
                }
                __half2 h0 = __floats2half2_rn(t4[0], t4[1]);
                __half2 h1 = __floats2half2_rn(t4[2], t4[3]);
                hbuf[jq * 2]     = *(uint32_t*)&h0;
                hbuf[jq * 2 + 1] = *(uint32_t*)&h1;
            }
        }
    }
    uint4* dst = (uint4*)(g_xth + (size_t)n * 64);
#pragma unroll
    for (int q = 0; q < 8; q++)
        dst[q] = make_uint4(hbuf[q*4], hbuf[q*4+1], hbuf[q*4+2], hbuf[q*4+3]);

    g_ssrc[n] = make_float4(ss[0], ss[1], ss[2], ss[3]);
    g_sdst[n] = make_float4(sd[0], sd[1], sd[2], sd[3]);
}

// ---------------------------------------------------------------------------
// Edge pass 1 (2 edges/thread): denom[col] += exps; count per row;
// store exps sequentially for kFill (no recompute there).
// (softmax-shift safely dropped: |score| <~ 17, exp within fp32 range)
// ---------------------------------------------------------------------------
__global__ void __launch_bounds__(256) kDenom(const int* __restrict__ ei, int E) {
    int t = blockIdx.x * blockDim.x + threadIdx.x;
    int e0 = t * 2;
    if (e0 >= E) return;
    bool two = (e0 + 1 < E);
    int2 rr = two ? __ldg((const int2*)(ei + e0))     : make_int2(__ldg(ei + e0), 0);
    int2 cc = two ? __ldg((const int2*)(ei + E + e0)) : make_int2(__ldg(ei + E + e0), 0);

    float4 s1a = g_ssrc[rr.x];
    float4 s2a = g_sdst[cc.x];
    float4 s1b, s2b;
    if (two) { s1b = g_ssrc[rr.y]; s2b = g_sdst[cc.y]; }

    {
        float a0 = __expf(lrelu(s1a.x + s2a.x));
        float a1 = __expf(lrelu(s1a.y + s2a.y));
        float a2 = __expf(lrelu(s1a.z + s2a.z));
        float a3 = __expf(lrelu(s1a.w + s2a.w));
        float* d = (float*)&g_denom[cc.x];
        asm volatile("red.global.add.v4.f32 [%0], {%1, %2, %3, %4};"
                     :: "l"(d), "f"(a0), "f"(a1), "f"(a2), "f"(a3) : "memory");
        atomicAdd(&g_cnt[rr.x], 1);
        g_e4[e0] = make_float4(a0, a1, a2, a3);
    }
    if (two) {
        float b0 = __expf(lrelu(s1b.x + s2b.x));
        float b1 = __expf(lrelu(s1b.y + s2b.y));
        float b2 = __expf(lrelu(s1b.z + s2b.z));
        float b3 = __expf(lrelu(s1b.w + s2b.w));
        float* d = (float*)&g_denom[cc.y];
        asm volatile("red.global.add.v4.f32 [%0], {%1, %2, %3, %4};"
                     :: "l"(d), "f"(b0), "f"(b1), "f"(b2), "f"(b3) : "memory");
        atomicAdd(&g_cnt[rr.y], 1);
        g_e4[e0 + 1] = make_float4(b0, b1, b2, b3);
    }
}

// ---------------------------------------------------------------------------
// Exclusive prefix scan of counts (warp-shuffle, atomic block offset).
// Also inverts denominators (1/H mean folded in).
// ---------------------------------------------------------------------------
__global__ void __launch_bounds__(1024) kScan(int n_nodes) {
    __shared__ int part[32];
    __shared__ int base;
    int tid = threadIdx.x;
    int lane = tid & 31, wid = tid >> 5;
    int i = blockIdx.x * 1024 + tid;
    int v = (i < n_nodes) ? g_cnt[i] : 0;
    int s = v;
#pragma unroll
    for (int d = 1; d < 32; d <<= 1) {
        int t = __shfl_up_sync(0xffffffffu, s, d);
        if (lane >= d) s += t;
    }
    if (lane == 31) part[wid] = s;
    __syncthreads();
    if (wid == 0) {
        int p = part[lane];
#pragma unroll
        for (int d = 1; d < 32; d <<= 1) {
            int t = __shfl_up_sync(0xffffffffu, p, d);
            if (lane >= d) p += t;
        }
        part[lane] = p;
        if (lane == 31) base = atomicAdd(&g_total, p);
    }
    __syncthreads();
    if (i < n_nodes) {
        int excl = base + s - v + (wid > 0 ? part[wid - 1] : 0);
        g_start[i]  = excl;
        g_cursor[i] = excl;
        float4 dn = g_denom[i];
        g_di[i] = make_float4(0.25f * __frcp_rn(dn.x + 1e-16f),
                              0.25f * __frcp_rn(dn.y + 1e-16f),
                              0.25f * __frcp_rn(dn.z + 1e-16f),
                              0.25f * __frcp_rn(dn.w + 1e-16f));
    }
}

// ---------------------------------------------------------------------------
// Edge pass 2 (2 edges/thread): w = stored e4 · di[c]; ONE random gather,
// no expf. Writes (col, w) into CSR slot.
// ---------------------------------------------------------------------------
__global__ void __launch_bounds__(256) kFill(const int* __restrict__ ei, int E) {
    int t = blockIdx.x * blockDim.x + threadIdx.x;
    int e0 = t * 2;
    if (e0 >= E) return;
    bool two = (e0 + 1 < E);
    int2 rr = two ? __ldg((const int2*)(ei + e0))     : make_int2(__ldg(ei + e0), 0);
    int2 cc = two ? __ldg((const int2*)(ei + E + e0)) : make_int2(__ldg(ei + E + e0), 0);

    float4 ea = g_e4[e0];
    float4 dia = __ldg(&g_di[cc.x]);
    float4 eb, dib;
    if (two) { eb = g_e4[e0 + 1]; dib = __ldg(&g_di[cc.y]); }

    {
        float w = ea.x * dia.x + ea.y * dia.y + ea.z * dia.z + ea.w * dia.w;
        int pos = atomicAdd(&g_cursor[rr.x], 1);
        g_cw[pos] = make_float2(__int_as_float(cc.x), w);
    }
    if (two) {
        float w = eb.x * dib.x + eb.y * dib.y + eb.z * dib.z + eb.w * dib.w;
        int pos = atomicAdd(&g_cursor[rr.y], 1);
        g_cw[pos] = make_float2(__int_as_float(cc.y), w);
    }
}

// ---------------------------------------------------------------------------
// Pull: one warp per row, lane owns 2 features (half2 gather, fp32 accum).
// Unrolled x8 (8 concurrent gathers) + x4 + scalar tail. Same access pattern
// as the verified 117us kernel, just wider.
// ---------------------------------------------------------------------------
__global__ void __launch_bounds__(256) kPull(float* __restrict__ out, int n_nodes) {
    int row = blockIdx.x * (blockDim.x >> 5) + (threadIdx.x >> 5);
    if (row >= n_nodes) return;
    int lane = threadIdx.x & 31;
    int start = g_start[row];
    int cnt   = g_cnt[row];

    const __half2* __restrict__ xt2 = (const __half2*)g_xth;
    float ax = 0.f, ay = 0.f, bx = 0.f, by = 0.f;

    int j = 0;
    for (; j + 8 <= cnt; j += 8) {
        float2 cw[8];
        __half2 xv[8];
#pragma unroll
        for (int u = 0; u < 8; u++) cw[u] = __ldg(&g_cw[start + j + u]);
#pragma unroll
        for (int u = 0; u < 8; u++)
            xv[u] = __ldg(&xt2[(size_t)__float_as_int(cw[u].x) * 32 + lane]);
#pragma unroll
        for (int u = 0; u < 8; u++) {
            float2 f = __half22float2(xv[u]);
            if (u & 1) { bx = fmaf(cw[u].y, f.x, bx); by = fmaf(cw[u].y, f.y, by); }
            else       { ax = fmaf(cw[u].y, f.x, ax); ay = fmaf(cw[u].y, f.y, ay); }
        }
    }
    for (; j + 4 <= cnt; j += 4) {
        float2 cw0 = __ldg(&g_cw[start + j]);
        float2 cw1 = __ldg(&g_cw[start + j + 1]);
        float2 cw2 = __ldg(&g_cw[start + j + 2]);
        float2 cw3 = __ldg(&g_cw[start + j + 3]);
        __half2 x0 = __ldg(&xt2[(size_t)__float_as_int(cw0.x) * 32 + lane]);
        __half2 x1 = __ldg(&xt2[(size_t)__float_as_int(cw1.x) * 32 + lane]);
        __half2 x2 = __ldg(&xt2[(size_t)__float_as_int(cw2.x) * 32 + lane]);
        __half2 x3 = __ldg(&xt2[(size_t)__float_as_int(cw3.x) * 32 + lane]);
        float2 f0 = __half22float2(x0);
        float2 f1 = __half22float2(x1);
        float2 f2 = __half22float2(x2);
        float2 f3 = __half22float2(x3);
        ax = fmaf(cw0.y, f0.x, ax); ay = fmaf(cw0.y, f0.y, ay);
        bx = fmaf(cw1.y, f1.x, bx); by = fmaf(cw1.y, f1.y, by);
        ax = fmaf(cw2.y, f2.x, ax); ay = fmaf(cw2.y, f2.y, ay);
        bx = fmaf(cw3.y, f3.x, bx); by = fmaf(cw3.y, f3.y, by);
    }
    for (; j < cnt; j++) {
        float2 cw = __ldg(&g_cw[start + j]);
        __half2 xv = __ldg(&xt2[(size_t)__float_as_int(cw.x) * 32 + lane]);
        float2 f = __half22float2(xv);
        ax = fmaf(cw.y, f.x, ax); ay = fmaf(cw.y, f.y, ay);
    }
    ((float2*)out)[(size_t)row * 32 + lane] = make_float2(ax + bx, ay + by);
}

// ---------------------------------------------------------------------------
// inputs: x[N*64] f32, edge_index[2*E] i32, edge_weight[E] f32 (unused),
//         W[64*64] f32, a[32] f32   |  output: out[N*64] f32
// ---------------------------------------------------------------------------
extern "C" void kernel_launch(void* const* d_in, const int* in_sizes, int n_in,
                              void* d_out, int out_size) {
    const float* x  = (const float*)d_in[0];
    const int*   ei = (const int*)d_in[1];
    const float* W  = (const float*)d_in[3];
    const float* a  = (const float*)d_in[4];
    float* out = (float*)d_out;

    int N = in_sizes[0] / 64;
    int E = in_sizes[2];
    int halfE = (E + 1) / 2;

    kZero<<<(N + 255) / 256, 256>>>(W, N);
    kNode<<<(N + 255) / 256, 256>>>(x, W, a, N);
    kDenom<<<(halfE + 255) / 256, 256>>>(ei, E);
    kScan<<<(N + 1023) / 1024, 1024>>>(N);
    kFill<<<(halfE + 255) / 256, 256>>>(ei, E);
    kPull<<<(N + 7) / 8, 256>>>(out, N);
}

// round 12
// speedup vs baseline: 1.0060x; 1.0060x over previous
#include <cuda_runtime.h>
#include <cuda_fp16.h>
#include <cstdint>

// Problem constants: N=100000, D=64, H=4, DK=16, E=1600000
#define MAXN 100000
#define MAXE 1600000

// xt = C1*x + C2*(x @ W^T)  where M^4, M=[[1,.25],[-.25,1]] (exact binary fracs)
#define C1 0.62890625f
#define C2 0.9375f
#define KI 1.56640625f   // C1 + C2 (exact), used when W == I
#define ALPHA 0.2f

struct __align__(32) CD { float4 sd; float4 di; };  // {sdst, 0.25/(denom+eps)}

// Scratch (static device arrays — no allocation allowed)
__device__ __half g_xth[MAXN * 64];   // transformed features, fp16 (12.8 MB)
__device__ float4 g_ssrc[MAXN];       // per-node per-head src score
__device__ float4 g_sdst[MAXN];       // per-node per-head dst score
__device__ float4 g_denom[MAXN];      // softmax denominator accumulators
__device__ CD     g_cd[MAXN];         // packed {sdst, inv-denom} for kFill
__device__ int    g_cnt[MAXN];        // out-degree by row
__device__ int    g_start[MAXN];      // CSR row start
__device__ int    g_cursor[MAXN];     // fill cursor
__device__ int    g_total;            // scan running offset
__device__ int    g_wflag;            // 0 iff W == identity
__device__ float2 g_cw[MAXE];         // per-edge (col, w)

__device__ __forceinline__ float lrelu(float v) {
    return v > 0.0f ? v : ALPHA * v;
}

// ---------------------------------------------------------------------------
// Zero per-replay state; also verify W == identity (first 4096 threads)
// ---------------------------------------------------------------------------
__global__ void kZero(const float* __restrict__ W, int n_nodes) {
    int i = blockIdx.x * blockDim.x + threadIdx.x;
    if (i == 0) { g_total = 0; g_wflag = 0; }
    if (i < 4096) {
        float expect = (i / 64 == i % 64) ? 1.0f : 0.0f;
        unsigned bad = __ballot_sync(0xffffffffu, W[i] != expect);
        if ((threadIdx.x & 31) == 0 && bad) atomicOr(&g_wflag, 1);
    }
    if (i < n_nodes) {
        g_denom[i] = make_float4(0.f, 0.f, 0.f, 0.f);
        g_cnt[i] = 0;
    }
}

// ---------------------------------------------------------------------------
// Per-node: xt = C1*x + C2*(x@W^T) (stored fp16); per-head scores (fp32).
// Fast path (W==I): xt = KI*x, pure streaming.
// ---------------------------------------------------------------------------
__global__ void __launch_bounds__(256) kNode(
    const float* __restrict__ x, const float* __restrict__ W,
    const float* __restrict__ a, int n_nodes)
{
    __shared__ float4 sW[1024];
    __shared__ float  sA[32];
    const bool ident = (g_wflag == 0);
    if (!ident) {
        for (int k = threadIdx.x; k < 1024; k += blockDim.x)
            sW[k] = ((const float4*)W)[k];
    }
    if (threadIdx.x < 32) sA[threadIdx.x] = a[threadIdx.x];
    __syncthreads();

    int n = blockIdx.x * blockDim.x + threadIdx.x;
    if (n >= n_nodes) return;

    float4 xr[16];
    const float4* xv = (const float4*)(x + (size_t)n * 64);
#pragma unroll
    for (int i = 0; i < 16; i++) xr[i] = xv[i];

    float ss[4] = {0.f, 0.f, 0.f, 0.f};
    float sd[4] = {0.f, 0.f, 0.f, 0.f};
    uint32_t hbuf[32];   // 64 halfs as 32 half2 words

    if (ident) {
#pragma unroll
        for (int jq = 0; jq < 16; jq++) {
            const int h = jq >> 2;
            float4 xq = xr[jq];
            float t0 = KI * xq.x, t1 = KI * xq.y, t2 = KI * xq.z, t3 = KI * xq.w;
            const int k = (jq & 3) * 4;
            ss[h] = fmaf(t0, sA[k],     fmaf(t1, sA[k+1],    fmaf(t2, sA[k+2],    fmaf(t3, sA[k+3],    ss[h]))));
            sd[h] = fmaf(t0, sA[16+k],  fmaf(t1, sA[16+k+1], fmaf(t2, sA[16+k+2], fmaf(t3, sA[16+k+3], sd[h]))));
            __half2 h0 = __floats2half2_rn(t0, t1);
            __half2 h1 = __floats2half2_rn(t2, t3);
            hbuf[jq * 2]     = *(uint32_t*)&h0;
            hbuf[jq * 2 + 1] = *(uint32_t*)&h1;
        }
    } else {
#pragma unroll
        for (int h = 0; h < 4; h++) {
#pragma unroll
            for (int kq = 0; kq < 4; kq++) {
                const int jq = h * 4 + kq;
                float4 xq = xr[jq];
                float t4[4];
#pragma unroll
                for (int m = 0; m < 4; m++) {
                    const int j = jq * 4 + m;
                    const float4* wr = &sW[j * 16];
                    float p = 0.f;
#pragma unroll
                    for (int i = 0; i < 16; i++) {
                        float4 w  = wr[i];
                        float4 xx = xr[i];
                        p = fmaf(xx.x, w.x, p);
                        p = fmaf(xx.y, w.y, p);
                        p = fmaf(xx.z, w.z, p);
                        p = fmaf(xx.w, w.w, p);
                    }
                    float xc = (m == 0) ? xq.x : (m == 1) ? xq.y : (m == 2) ? xq.z : xq.w;
                    float t  = fmaf(C2, p, C1 * xc);
                    const int k = kq * 4 + m;
                    ss[h] = fmaf(t, sA[k],      ss[h]);
                    sd[h] = fmaf(t, sA[16 + k], sd[h]);
                    t4[m] = t;
                }
                __half2 h0 = __floats2half2_rn(t4[0], t4[1]);
                __half2 h1 = __floats2half2_rn(t4[2], t4[3]);
                hbuf[jq * 2]     = *(uint32_t*)&h0;
                hbuf[jq * 2 + 1] = *(uint32_t*)&h1;
            }
        }
    }
    uint4* dst = (uint4*)(g_xth + (size_t)n * 64);
#pragma unroll
    for (int q = 0; q < 8; q++)
        dst[q] = make_uint4(hbuf[q*4], hbuf[q*4+1], hbuf[q*4+2], hbuf[q*4+3]);

    g_ssrc[n] = make_float4(ss[0], ss[1], ss[2], ss[3]);
    g_sdst[n] = make_float4(sd[0], sd[1], sd[2], sd[3]);
}

// ---------------------------------------------------------------------------
// Edge pass 1 (2 edges/thread): denom[col] += exp(leaky(.)); count per row.
// (softmax-shift safely dropped: |score| <~ 17, exp within fp32 range)
// ---------------------------------------------------------------------------
__global__ void __launch_bounds__(256) kDenom(const int* __restrict__ ei, int E) {
    int t = blockIdx.x * blockDim.x + threadIdx.x;
    int e0 = t * 2;
    if (e0 >= E) return;
    bool two = (e0 + 1 < E);
    int2 rr = two ? __ldg((const int2*)(ei + e0))     : make_int2(__ldg(ei + e0), 0);
    int2 cc = two ? __ldg((const int2*)(ei + E + e0)) : make_int2(__ldg(ei + E + e0), 0);

    float4 s1a = g_ssrc[rr.x];
    float4 s2a = g_sdst[cc.x];
    float4 s1b, s2b;
    if (two) { s1b = g_ssrc[rr.y]; s2b = g_sdst[cc.y]; }

    {
        float a0 = __expf(lrelu(s1a.x + s2a.x));
        float a1 = __expf(lrelu(s1a.y + s2a.y));
        float a2 = __expf(lrelu(s1a.z + s2a.z));
        float a3 = __expf(lrelu(s1a.w + s2a.w));
        float* d = (float*)&g_denom[cc.x];
        asm volatile("red.global.add.v4.f32 [%0], {%1, %2, %3, %4};"
                     :: "l"(d), "f"(a0), "f"(a1), "f"(a2), "f"(a3) : "memory");
        atomicAdd(&g_cnt[rr.x], 1);
    }
    if (two) {
        float b0 = __expf(lrelu(s1b.x + s2b.x));
        float b1 = __expf(lrelu(s1b.y + s2b.y));
        float b2 = __expf(lrelu(s1b.z + s2b.z));
        float b3 = __expf(lrelu(s1b.w + s2b.w));
        float* d = (float*)&g_denom[cc.y];
        asm volatile("red.global.add.v4.f32 [%0], {%1, %2, %3, %4};"
                     :: "l"(d), "f"(b0), "f"(b1), "f"(b2), "f"(b3) : "memory");
        atomicAdd(&g_cnt[rr.y], 1);
    }
}

// ---------------------------------------------------------------------------
// Exclusive prefix scan of counts (warp-shuffle, atomic block offset).
// Also packs {sdst, 0.25/(denom+eps)} into g_cd for kFill's single gather.
// ---------------------------------------------------------------------------
__global__ void __launch_bounds__(1024) kScan(int n_nodes) {
    __shared__ int part[32];
    __shared__ int base;
    int tid = threadIdx.x;
    int lane = tid & 31, wid = tid >> 5;
    int i = blockIdx.x * 1024 + tid;
    int v = (i < n_nodes) ? g_cnt[i] : 0;
    int s = v;
#pragma unroll
    for (int d = 1; d < 32; d <<= 1) {
        int t = __shfl_up_sync(0xffffffffu, s, d);
        if (lane >= d) s += t;
    }
    if (lane == 31) part[wid] = s;
    __syncthreads();
    if (wid == 0) {
        int p = part[lane];
#pragma unroll
        for (int d = 1; d < 32; d <<= 1) {
            int t = __shfl_up_sync(0xffffffffu, p, d);
            if (lane >= d) p += t;
        }
        part[lane] = p;
        if (lane == 31) base = atomicAdd(&g_total, p);
    }
    __syncthreads();
    if (i < n_nodes) {
        int excl = base + s - v + (wid > 0 ? part[wid - 1] : 0);
        g_start[i]  = excl;
        g_cursor[i] = excl;
        float4 dn = g_denom[i];
        g_cd[i].sd = g_sdst[i];
        g_cd[i].di = make_float4(0.25f * __frcp_rn(dn.x + 1e-16f),
                                 0.25f * __frcp_rn(dn.y + 1e-16f),
                                 0.25f * __frcp_rn(dn.z + 1e-16f),
                                 0.25f * __frcp_rn(dn.w + 1e-16f));
    }
}

// ---------------------------------------------------------------------------
// Edge pass 2 (2 edges/thread): w once per edge; single 32B c-side gather.
// ---------------------------------------------------------------------------
__global__ void __launch_bounds__(256) kFill(const int* __restrict__ ei, int E) {
    int t = blockIdx.x * blockDim.x + threadIdx.x;
    int e0 = t * 2;
    if (e0 >= E) return;
    bool two = (e0 + 1 < E);
    int2 rr = two ? __ldg((const int2*)(ei + e0))     : make_int2(__ldg(ei + e0), 0);
    int2 cc = two ? __ldg((const int2*)(ei + E + e0)) : make_int2(__ldg(ei + E + e0), 0);

    float4 s1a = g_ssrc[rr.x];
    float4 sda = g_cd[cc.x].sd;
    float4 dia = g_cd[cc.x].di;
    float4 s1b, sdb, dib;
    if (two) { s1b = g_ssrc[rr.y]; sdb = g_cd[cc.y].sd; dib = g_cd[cc.y].di; }

    {
        float w = __expf(lrelu(s1a.x + sda.x)) * dia.x +
                  __expf(lrelu(s1a.y + sda.y)) * dia.y +
                  __expf(lrelu(s1a.z + sda.z)) * dia.z +
                  __expf(lrelu(s1a.w + sda.w)) * dia.w;
        int pos = atomicAdd(&g_cursor[rr.x], 1);
        g_cw[pos] = make_float2(__int_as_float(cc.x), w);
    }
    if (two) {
        float w = __expf(lrelu(s1b.x + sdb.x)) * dib.x +
                  __expf(lrelu(s1b.y + sdb.y)) * dib.y +
                  __expf(lrelu(s1b.z + sdb.z)) * dib.z +
                  __expf(lrelu(s1b.w + sdb.w)) * dib.w;
        int pos = atomicAdd(&g_cursor[rr.y], 1);
        g_cw[pos] = make_float2(__int_as_float(cc.y), w);
    }
}

// ---------------------------------------------------------------------------
// Pull: one warp per row, lane owns 2 features (half2 gather, fp32 accum).
// ONE CHANGE vs the 116.9us kernel: main loop widened to 8 concurrent
// gathers using explicit scalar registers (no arrays).
// ---------------------------------------------------------------------------
__global__ void __launch_bounds__(256) kPull(float* __restrict__ out, int n_nodes) {
    int row = blockIdx.x * (blockDim.x >> 5) + (threadIdx.x >> 5);
    if (row >= n_nodes) return;
    int lane = threadIdx.x & 31;
    int start = g_start[row];
    int cnt   = g_cnt[row];

    const __half2* __restrict__ xt2 = (const __half2*)g_xth;
    float ax = 0.f, ay = 0.f, bx = 0.f, by = 0.f;

    int j = 0;
    for (; j + 8 <= cnt; j += 8) {
        float2 cw0 = __ldg(&g_cw[start + j]);
        float2 cw1 = __ldg(&g_cw[start + j + 1]);
        float2 cw2 = __ldg(&g_cw[start + j + 2]);
        float2 cw3 = __ldg(&g_cw[start + j + 3]);
        float2 cw4 = __ldg(&g_cw[start + j + 4]);
        float2 cw5 = __ldg(&g_cw[start + j + 5]);
        float2 cw6 = __ldg(&g_cw[start + j + 6]);
        float2 cw7 = __ldg(&g_cw[start + j + 7]);
        __half2 x0 = __ldg(&xt2[(size_t)__float_as_int(cw0.x) * 32 + lane]);
        __half2 x1 = __ldg(&xt2[(size_t)__float_as_int(cw1.x) * 32 + lane]);
        __half2 x2 = __ldg(&xt2[(size_t)__float_as_int(cw2.x) * 32 + lane]);
        __half2 x3 = __ldg(&xt2[(size_t)__float_as_int(cw3.x) * 32 + lane]);
        __half2 x4 = __ldg(&xt2[(size_t)__float_as_int(cw4.x) * 32 + lane]);
        __half2 x5 = __ldg(&xt2[(size_t)__float_as_int(cw5.x) * 32 + lane]);
        __half2 x6 = __ldg(&xt2[(size_t)__float_as_int(cw6.x) * 32 + lane]);
        __half2 x7 = __ldg(&xt2[(size_t)__float_as_int(cw7.x) * 32 + lane]);
        float2 f0 = __half22float2(x0);
        float2 f1 = __half22float2(x1);
        float2 f2 = __half22float2(x2);
        float2 f3 = __half22float2(x3);
        float2 f4 = __half22float2(x4);
        float2 f5 = __half22float2(x5);
        float2 f6 = __half22float2(x6);
        float2 f7 = __half22float2(x7);
        ax = fmaf(cw0.y, f0.x, ax); ay = fmaf(cw0.y, f0.y, ay);
        bx = fmaf(cw1.y, f1.x, bx); by = fmaf(cw1.y, f1.y, by);
        ax = fmaf(cw2.y, f2.x, ax); ay = fmaf(cw2.y, f2.y, ay);
        bx = fmaf(cw3.y, f3.x, bx); by = fmaf(cw3.y, f3.y, by);
        ax = fmaf(cw4.y, f4.x, ax); ay = fmaf(cw4.y, f4.y, ay);
        bx = fmaf(cw5.y, f5.x, bx); by = fmaf(cw5.y, f5.y, by);
        ax = fmaf(cw6.y, f6.x, ax); ay = fmaf(cw6.y, f6.y, ay);
        bx = fmaf(cw7.y, f7.x, bx); by = fmaf(cw7.y, f7.y, by);
    }
    for (; j + 4 <= cnt; j += 4) {
        float2 cw0 = __ldg(&g_cw[start + j]);
        float2 cw1 = __ldg(&g_cw[start + j + 1]);
        float2 cw2 = __ldg(&g_cw[start + j + 2]);
        float2 cw3 = __ldg(&g_cw[start + j + 3]);
        __half2 x0 = __ldg(&xt2[(size_t)__float_as_int(cw0.x) * 32 + lane]);
        __half2 x1 = __ldg(&xt2[(size_t)__float_as_int(cw1.x) * 32 + lane]);
        __half2 x2 = __ldg(&xt2[(size_t)__float_as_int(cw2.x) * 32 + lane]);
        __half2 x3 = __ldg(&xt2[(size_t)__float_as_int(cw3.x) * 32 + lane]);
        float2 f0 = __half22float2(x0);
        float2 f1 = __half22float2(x1);
        float2 f2 = __half22float2(x2);
        float2 f3 = __half22float2(x3);
        ax = fmaf(cw0.y, f0.x, ax); ay = fmaf(cw0.y, f0.y, ay);
        bx = fmaf(cw1.y, f1.x, bx); by = fmaf(cw1.y, f1.y, by);
        ax = fmaf(cw2.y, f2.x, ax); ay = fmaf(cw2.y, f2.y, ay);
        bx = fmaf(cw3.y, f3.x, bx); by = fmaf(cw3.y, f3.y, by);
    }
    for (; j < cnt; j++) {
        float2 cw = __ldg(&g_cw[start + j]);
        __half2 xv = __ldg(&xt2[(size_t)__float_as_int(cw.x) * 32 + lane]);
        float2 f = __half22float2(xv);
        ax = fmaf(cw.y, f.x, ax); ay = fmaf(cw.y, f.y, ay);
    }
    ((float2*)out)[(size_t)row * 32 + lane] = make_float2(ax + bx, ay + by);
}

// ---------------------------------------------------------------------------
// inputs: x[N*64] f32, edge_index[2*E] i32, edge_weight[E] f32 (unused),
//         W[64*64] f32, a[32] f32   |  output: out[N*64] f32
// ---------------------------------------------------------------------------
extern "C" void kernel_launch(void* const* d_in, const int* in_sizes, int n_in,
                              void* d_out, int out_size) {
    const float* x  = (const float*)d_in[0];
    const int*   ei = (const int*)d_in[1];
    const float* W  = (const float*)d_in[3];
    const float* a  = (const float*)d_in[4];
    float* out = (float*)d_out;

    int N = in_sizes[0] / 64;
    int E = in_sizes[2];
    int halfE = (E + 1) / 2;

    kZero<<<(N + 255) / 256, 256>>>(W, N);
    kNode<<<(N + 255) / 256, 256>>>(x, W, a, N);
    kDenom<<<(halfE + 255) / 256, 256>>>(ei, E);
    kScan<<<(N + 1023) / 1024, 1024>>>(N);
    kFill<<<(halfE + 255) / 256, 256>>>(ei, E);
    kPull<<<(N + 7) / 8, 256>>>(out, N);
}

// round 13
// speedup vs baseline: 1.0710x; 1.0646x over previous
#include <cuda_runtime.h>
#include <cuda_fp16.h>
#include <cstdint>

// Problem constants: N=100000, D=64, H=4, DK=16, E=1600000
#define MAXN 100000
#define MAXE 1600000

// xt = C1*x + C2*(x @ W^T)  where M^4, M=[[1,.25],[-.25,1]] (exact binary fracs)
#define C1 0.62890625f
#define C2 0.9375f
#define KI 1.56640625f   // C1 + C2 (exact), used when W == I
#define ALPHA 0.2f

struct __align__(32) CD { float4 sd; float4 di; };  // {sdst, 0.25/(denom+eps)}

// Scratch (static device arrays — no allocation allowed)
__device__ __half g_xth[MAXN * 64];   // transformed features, fp16 (12.8 MB)
__device__ float4 g_ssrc[MAXN];       // per-node per-head src score
__device__ float4 g_sdst[MAXN];       // per-node per-head dst score
__device__ float4 g_denom[MAXN];      // softmax denominator accumulators
__device__ CD     g_cd[MAXN];         // packed {sdst, inv-denom} for kFill
__device__ int    g_cnt[MAXN];        // out-degree by row
__device__ int    g_start[MAXN];      // CSR row start
__device__ int    g_total;            // scan running offset
__device__ int    g_wflag;            // 0 iff W == identity
__device__ int    g_eidx[MAXE];       // within-row occurrence index (from kDenom)
__device__ float2 g_cw[MAXE];         // per-edge (col, w)

__device__ __forceinline__ float lrelu(float v) {
    return v > 0.0f ? v : ALPHA * v;
}

// ---------------------------------------------------------------------------
// Zero per-replay state; also verify W == identity (first 4096 threads)
// ---------------------------------------------------------------------------
__global__ void kZero(const float* __restrict__ W, int n_nodes) {
    int i = blockIdx.x * blockDim.x + threadIdx.x;
    if (i == 0) { g_total = 0; g_wflag = 0; }
    if (i < 4096) {
        float expect = (i / 64 == i % 64) ? 1.0f : 0.0f;
        unsigned bad = __ballot_sync(0xffffffffu, W[i] != expect);
        if ((threadIdx.x & 31) == 0 && bad) atomicOr(&g_wflag, 1);
    }
    if (i < n_nodes) {
        g_denom[i] = make_float4(0.f, 0.f, 0.f, 0.f);
        g_cnt[i] = 0;
    }
}

// ---------------------------------------------------------------------------
// Per-node: xt = C1*x + C2*(x@W^T) (stored fp16); per-head scores (fp32).
// Fast path (W==I): xt = KI*x, pure streaming.
// ---------------------------------------------------------------------------
__global__ void __launch_bounds__(256) kNode(
    const float* __restrict__ x, const float* __restrict__ W,
    const float* __restrict__ a, int n_nodes)
{
    __shared__ float4 sW[1024];
    __shared__ float  sA[32];
    const bool ident = (g_wflag == 0);
    if (!ident) {
        for (int k = threadIdx.x; k < 1024; k += blockDim.x)
            sW[k] = ((const float4*)W)[k];
    }
    if (threadIdx.x < 32) sA[threadIdx.x] = a[threadIdx.x];
    __syncthreads();

    int n = blockIdx.x * blockDim.x + threadIdx.x;
    if (n >= n_nodes) return;

    float4 xr[16];
    const float4* xv = (const float4*)(x + (size_t)n * 64);
#pragma unroll
    for (int i = 0; i < 16; i++) xr[i] = xv[i];

    float ss[4] = {0.f, 0.f, 0.f, 0.f};
    float sd[4] = {0.f, 0.f, 0.f, 0.f};
    uint32_t hbuf[32];   // 64 halfs as 32 half2 words

    if (ident) {
#pragma unroll
        for (int jq = 0; jq < 16; jq++) {
            const int h = jq >> 2;
            float4 xq = xr[jq];
            float t0 = KI * xq.x, t1 = KI * xq.y, t2 = KI * xq.z, t3 = KI * xq.w;
            const int k = (jq & 3) * 4;
            ss[h] = fmaf(t0, sA[k],     fmaf(t1, sA[k+1],    fmaf(t2, sA[k+2],    fmaf(t3, sA[k+3],    ss[h]))));
            sd[h] = fmaf(t0, sA[16+k],  fmaf(t1, sA[16+k+1], fmaf(t2, sA[16+k+2], fmaf(t3, sA[16+k+3], sd[h]))));
            __half2 h0 = __floats2half2_rn(t0, t1);
            __half2 h1 = __floats2half2_rn(t2, t3);
            hbuf[jq * 2]     = *(uint32_t*)&h0;
            hbuf[jq * 2 + 1] = *(uint32_t*)&h1;
        }
    } else {
#pragma unroll
        for (int h = 0; h < 4; h++) {
#pragma unroll
            for (int kq = 0; kq < 4; kq++) {
                const int jq = h * 4 + kq;
                float4 xq = xr[jq];
                float t4[4];
#pragma unroll
                for (int m = 0; m < 4; m++) {
                    const int j = jq * 4 + m;
                    const float4* wr = &sW[j * 16];
                    float p = 0.f;
#pragma unroll
                    for (int i = 0; i < 16; i++) {
                        float4 w  = wr[i];
                        float4 xx = xr[i];
                        p = fmaf(xx.x, w.x, p);
                        p = fmaf(xx.y, w.y, p);
                        p = fmaf(xx.z, w.z, p);
                        p = fmaf(xx.w, w.w, p);
                    }
                    float xc = (m == 0) ? xq.x : (m == 1) ? xq.y : (m == 2) ? xq.z : xq.w;
                    float t  = fmaf(C2, p, C1 * xc);
                    const int k = kq * 4 + m;
                    ss[h] = fmaf(t, sA[k],      ss[h]);
                    sd[h] = fmaf(t, sA[16 + k], sd[h]);
                    t4[m] = t;
                }
                __half2 h0 = __floats2half2_rn(t4[0], t4[1]);
                __half2 h1 = __floats2half2_rn(t4[2], t4[3]);
                hbuf[jq * 2]     = *(uint32_t*)&h0;
                hbuf[jq * 2 + 1] = *(uint32_t*)&h1;
            }
        }
    }
    uint4* dst = (uint4*)(g_xth + (size_t)n * 64);
#pragma unroll
    for (int q = 0; q < 8; q++)
        dst[q] = make_uint4(hbuf[q*4], hbuf[q*4+1], hbuf[q*4+2], hbuf[q*4+3]);

    g_ssrc[n] = make_float4(ss[0], ss[1], ss[2], ss[3]);
    g_sdst[n] = make_float4(sd[0], sd[1], sd[2], sd[3]);
}

// ---------------------------------------------------------------------------
// Edge pass 1 (2 edges/thread): denom[col] += exp(leaky(.)); count per row,
// KEEPING the atomic's return as the within-row slot index (g_eidx).
// (softmax-shift safely dropped: |score| <~ 17, exp within fp32 range)
// ---------------------------------------------------------------------------
__global__ void __launch_bounds__(256) kDenom(const int* __restrict__ ei, int E) {
    int t = blockIdx.x * blockDim.x + threadIdx.x;
    int e0 = t * 2;
    if (e0 >= E) return;
    bool two = (e0 + 1 < E);
    int2 rr = two ? __ldg((const int2*)(ei + e0))     : make_int2(__ldg(ei + e0), 0);
    int2 cc = two ? __ldg((const int2*)(ei + E + e0)) : make_int2(__ldg(ei + E + e0), 0);

    float4 s1a = g_ssrc[rr.x];
    float4 s2a = g_sdst[cc.x];
    float4 s1b, s2b;
    if (two) { s1b = g_ssrc[rr.y]; s2b = g_sdst[cc.y]; }

    {
        float a0 = __expf(lrelu(s1a.x + s2a.x));
        float a1 = __expf(lrelu(s1a.y + s2a.y));
        float a2 = __expf(lrelu(s1a.z + s2a.z));
        float a3 = __expf(lrelu(s1a.w + s2a.w));
        float* d = (float*)&g_denom[cc.x];
        asm volatile("red.global.add.v4.f32 [%0], {%1, %2, %3, %4};"
                     :: "l"(d), "f"(a0), "f"(a1), "f"(a2), "f"(a3) : "memory");
        g_eidx[e0] = atomicAdd(&g_cnt[rr.x], 1);
    }
    if (two) {
        float b0 = __expf(lrelu(s1b.x + s2b.x));
        float b1 = __expf(lrelu(s1b.y + s2b.y));
        float b2 = __expf(lrelu(s1b.z + s2b.z));
        float b3 = __expf(lrelu(s1b.w + s2b.w));
        float* d = (float*)&g_denom[cc.y];
        asm volatile("red.global.add.v4.f32 [%0], {%1, %2, %3, %4};"
                     :: "l"(d), "f"(b0), "f"(b1), "f"(b2), "f"(b3) : "memory");
        g_eidx[e0 + 1] = atomicAdd(&g_cnt[rr.y], 1);
    }
}

// ---------------------------------------------------------------------------
// Exclusive prefix scan of counts (warp-shuffle, atomic block offset; 256/blk).
// Also packs {sdst, 0.25/(denom+eps)} into g_cd for kFill's single gather.
// ---------------------------------------------------------------------------
__global__ void __launch_bounds__(256) kScan(int n_nodes) {
    __shared__ int part[8];
    __shared__ int base;
    int tid = threadIdx.x;
    int lane = tid & 31, wid = tid >> 5;
    int i = blockIdx.x * 256 + tid;
    int v = (i < n_nodes) ? g_cnt[i] : 0;
    int s = v;
#pragma unroll
    for (int d = 1; d < 32; d <<= 1) {
        int t = __shfl_up_sync(0xffffffffu, s, d);
        if (lane >= d) s += t;
    }
    if (lane == 31) part[wid] = s;
    __syncthreads();
    if (wid == 0 && lane < 8) {
        int p = part[lane];
#pragma unroll
        for (int d = 1; d < 8; d <<= 1) {
            int t = __shfl_up_sync(0xffu, p, d);
            if (lane >= d) p += t;
        }
        part[lane] = p;
        if (lane == 7) base = atomicAdd(&g_total, p);
    }
    __syncthreads();
    if (i < n_nodes) {
        int excl = base + s - v + (wid > 0 ? part[wid - 1] : 0);
        g_start[i] = excl;
        float4 dn = g_denom[i];
        g_cd[i].sd = g_sdst[i];
        g_cd[i].di = make_float4(0.25f * __frcp_rn(dn.x + 1e-16f),
                                 0.25f * __frcp_rn(dn.y + 1e-16f),
                                 0.25f * __frcp_rn(dn.z + 1e-16f),
                                 0.25f * __frcp_rn(dn.w + 1e-16f));
    }
}

// ---------------------------------------------------------------------------
// Edge pass 2 (2 edges/thread): w once per edge; single 32B c-side gather;
// CSR slot computed WITHOUT atomics: pos = start[r] + eidx[e].
// ---------------------------------------------------------------------------
__global__ void __launch_bounds__(256) kFill(const int* __restrict__ ei, int E) {
    int t = blockIdx.x * blockDim.x + threadIdx.x;
    int e0 = t * 2;
    if (e0 >= E) return;
    bool two = (e0 + 1 < E);
    int2 rr = two ? __ldg((const int2*)(ei + e0))     : make_int2(__ldg(ei + e0), 0);
    int2 cc = two ? __ldg((const int2*)(ei + E + e0)) : make_int2(__ldg(ei + E + e0), 0);

    float4 s1a = g_ssrc[rr.x];
    float4 sda = g_cd[cc.x].sd;
    float4 dia = g_cd[cc.x].di;
    float4 s1b, sdb, dib;
    if (two) { s1b = g_ssrc[rr.y]; sdb = g_cd[cc.y].sd; dib = g_cd[cc.y].di; }

    {
        float w = __expf(lrelu(s1a.x + sda.x)) * dia.x +
                  __expf(lrelu(s1a.y + sda.y)) * dia.y +
                  __expf(lrelu(s1a.z + sda.z)) * dia.z +
                  __expf(lrelu(s1a.w + sda.w)) * dia.w;
        int pos = __ldg(&g_start[rr.x]) + g_eidx[e0];
        g_cw[pos] = make_float2(__int_as_float(cc.x), w);
    }
    if (two) {
        float w = __expf(lrelu(s1b.x + sdb.x)) * dib.x +
                  __expf(lrelu(s1b.y + sdb.y)) * dib.y +
                  __expf(lrelu(s1b.z + sdb.z)) * dib.z +
                  __expf(lrelu(s1b.w + sdb.w)) * dib.w;
        int pos = __ldg(&g_start[rr.y]) + g_eidx[e0 + 1];
        g_cw[pos] = make_float2(__int_as_float(cc.y), w);
    }
}

// ---------------------------------------------------------------------------
// Pull: one warp per row, lane owns 2 features (half2 gather, fp32 accum).
// Unrolled x4 with independent accumulators (FROZEN — verified best).
// ---------------------------------------------------------------------------
__global__ void __launch_bounds__(256) kPull(float* __restrict__ out, int n_nodes) {
    int row = blockIdx.x * (blockDim.x >> 5) + (threadIdx.x >> 5);
    if (row >= n_nodes) return;
    int lane = threadIdx.x & 31;
    int start = g_start[row];
    int cnt   = g_cnt[row];

    const __half2* __restrict__ xt2 = (const __half2*)g_xth;
    float ax = 0.f, ay = 0.f, bx = 0.f, by = 0.f;

    int j = 0;
    for (; j + 4 <= cnt; j += 4) {
        float2 cw0 = __ldg(&g_cw[start + j]);
        float2 cw1 = __ldg(&g_cw[start + j + 1]);
        float2 cw2 = __ldg(&g_cw[start + j + 2]);
        float2 cw3 = __ldg(&g_cw[start + j + 3]);
        __half2 x0 = __ldg(&xt2[(size_t)__float_as_int(cw0.x) * 32 + lane]);
        __half2 x1 = __ldg(&xt2[(size_t)__float_as_int(cw1.x) * 32 + lane]);
        __half2 x2 = __ldg(&xt2[(size_t)__float_as_int(cw2.x) * 32 + lane]);
        __half2 x3 = __ldg(&xt2[(size_t)__float_as_int(cw3.x) * 32 + lane]);
        float2 f0 = __half22float2(x0);
        float2 f1 = __half22float2(x1);
        float2 f2 = __half22float2(x2);
        float2 f3 = __half22float2(x3);
        ax = fmaf(cw0.y, f0.x, ax); ay = fmaf(cw0.y, f0.y, ay);
        bx = fmaf(cw1.y, f1.x, bx); by = fmaf(cw1.y, f1.y, by);
        ax = fmaf(cw2.y, f2.x, ax); ay = fmaf(cw2.y, f2.y, ay);
        bx = fmaf(cw3.y, f3.x, bx); by = fmaf(cw3.y, f3.y, by);
    }
    for (; j < cnt; j++) {
        float2 cw = __ldg(&g_cw[start + j]);
        __half2 xv = __ldg(&xt2[(size_t)__float_as_int(cw.x) * 32 + lane]);
        float2 f = __half22float2(xv);
        ax = fmaf(cw.y, f.x, ax); ay = fmaf(cw.y, f.y, ay);
    }
    ((float2*)out)[(size_t)row * 32 + lane] = make_float2(ax + bx, ay + by);
}

// ---------------------------------------------------------------------------
// inputs: x[N*64] f32, edge_index[2*E] i32, edge_weight[E] f32 (unused),
//         W[64*64] f32, a[32] f32   |  output: out[N*64] f32
// ---------------------------------------------------------------------------
extern "C" void kernel_launch(void* const* d_in, const int* in_sizes, int n_in,
                              void* d_out, int out_size) {
    const float* x  = (const float*)d_in[0];
    const int*   ei = (const int*)d_in[1];
    const float* W  = (const float*)d_in[3];
    const float* a  = (const float*)d_in[4];
    float* out = (float*)d_out;

    int N = in_sizes[0] / 64;
    int E = in_sizes[2];
    int halfE = (E + 1) / 2;

    kZero<<<(N + 255) / 256, 256>>>(W, N);
    kNode<<<(N + 255) / 256, 256>>>(x, W, a, N);
    kDenom<<<(halfE + 255) / 256, 256>>>(ei, E);
    kScan<<<(N + 255) / 256, 256>>>(N);
    kFill<<<(halfE + 255) / 256, 256>>>(ei, E);
    kPull<<<(N + 7) / 8, 256>>>(out, N);
}

// round 15
// speedup vs baseline: 1.0772x; 1.0059x over previous
#include <cuda_runtime.h>
#include <cuda_fp16.h>
#include <cstdint>

// Problem constants: N=100000, D=64, H=4, DK=16, E=1600000
#define MAXN 100000
#define MAXE 1600000

// xt = C1*x + C2*(x @ W^T)  where M^4, M=[[1,.25],[-.25,1]] (exact binary fracs)
#define C1 0.62890625f
#define C2 0.9375f
#define KI 1.56640625f   // C1 + C2 (exact), used when W == I
#define ALPHA 0.2f

struct __align__(32) CD { float4 sd; float4 di; };  // {sdst, 0.25/(denom+eps)}

// Scratch (static device arrays — no allocation allowed)
__device__ __half g_xth[MAXN * 64];   // transformed features, fp16 (12.8 MB)
__device__ float4 g_ssrc[MAXN];       // per-node per-head src score
__device__ float4 g_sdst[MAXN];       // per-node per-head dst score
__device__ float4 g_denom[MAXN];      // softmax denominator accumulators
__device__ CD     g_cd[MAXN];         // packed {sdst, inv-denom} for kFill
__device__ int    g_cnt[MAXN];        // out-degree by row
__device__ int    g_start[MAXN];      // CSR row start
__device__ int    g_total;            // scan running offset
__device__ int    g_wflag;            // 0 iff W == identity
__device__ int    g_eidx[MAXE];       // within-row occurrence index (from kDenom)
__device__ float2 g_cw[MAXE];         // per-edge (col, w)

__device__ __forceinline__ float lrelu(float v) {
    return v > 0.0f ? v : ALPHA * v;
}

// ---------------------------------------------------------------------------
// Zero per-replay state; also verify W == identity (first 4096 threads)
// ---------------------------------------------------------------------------
__global__ void kZero(const float* __restrict__ W, int n_nodes) {
    int i = blockIdx.x * blockDim.x + threadIdx.x;
    if (i == 0) { g_total = 0; g_wflag = 0; }
    if (i < 4096) {
        float expect = (i / 64 == i % 64) ? 1.0f : 0.0f;
        unsigned bad = __ballot_sync(0xffffffffu, W[i] != expect);
        if ((threadIdx.x & 31) == 0 && bad) atomicOr(&g_wflag, 1);
    }
    if (i < n_nodes) {
        g_denom[i] = make_float4(0.f, 0.f, 0.f, 0.f);
        g_cnt[i] = 0;
    }
}

// ---------------------------------------------------------------------------
// Per-node: xt = C1*x + C2*(x@W^T) (stored fp16); per-head scores (fp32).
// Fast path (W==I): xt = KI*x, pure streaming.
// ---------------------------------------------------------------------------
__global__ void __launch_bounds__(256) kNode(
    const float* __restrict__ x, const float* __restrict__ W,
    const float* __restrict__ a, int n_nodes)
{
    __shared__ float4 sW[1024];
    __shared__ float  sA[32];
    const bool ident = (g_wflag == 0);
    if (!ident) {
        for (int k = threadIdx.x; k < 1024; k += blockDim.x)
            sW[k] = ((const float4*)W)[k];
    }
    if (threadIdx.x < 32) sA[threadIdx.x] = a[threadIdx.x];
    __syncthreads();

    int n = blockIdx.x * blockDim.x + threadIdx.x;
    if (n >= n_nodes) return;

    float4 xr[16];
    const float4* xv = (const float4*)(x + (size_t)n * 64);
#pragma unroll
    for (int i = 0; i < 16; i++) xr[i] = xv[i];

    float ss[4] = {0.f, 0.f, 0.f, 0.f};
    float sd[4] = {0.f, 0.f, 0.f, 0.f};
    uint32_t hbuf[32];   // 64 halfs as 32 half2 words

    if (ident) {
#pragma unroll
        for (int jq = 0; jq < 16; jq++) {
            const int h = jq >> 2;
            float4 xq = xr[jq];
            float t0 = KI * xq.x, t1 = KI * xq.y, t2 = KI * xq.z, t3 = KI * xq.w;
            const int k = (jq & 3) * 4;
            ss[h] = fmaf(t0, sA[k],     fmaf(t1, sA[k+1],    fmaf(t2, sA[k+2],    fmaf(t3, sA[k+3],    ss[h]))));
            sd[h] = fmaf(t0, sA[16+k],  fmaf(t1, sA[16+k+1], fmaf(t2, sA[16+k+2], fmaf(t3, sA[16+k+3], sd[h]))));
            __half2 h0 = __floats2half2_rn(t0, t1);
            __half2 h1 = __floats2half2_rn(t2, t3);
            hbuf[jq * 2]     = *(uint32_t*)&h0;
            hbuf[jq * 2 + 1] = *(uint32_t*)&h1;
        }
    } else {
#pragma unroll
        for (int h = 0; h < 4; h++) {
#pragma unroll
            for (int kq = 0; kq < 4; kq++) {
                const int jq = h * 4 + kq;
                float4 xq = xr[jq];
                float t4[4];
#pragma unroll
                for (int m = 0; m < 4; m++) {
                    const int j = jq * 4 + m;
                    const float4* wr = &sW[j * 16];
                    float p = 0.f;
#pragma unroll
                    for (int i = 0; i < 16; i++) {
                        float4 w  = wr[i];
                        float4 xx = xr[i];
                        p = fmaf(xx.x, w.x, p);
                        p = fmaf(xx.y, w.y, p);
                        p = fmaf(xx.z, w.z, p);
                        p = fmaf(xx.w, w.w, p);
                    }
                    float xc = (m == 0) ? xq.x : (m == 1) ? xq.y : (m == 2) ? xq.z : xq.w;
                    float t  = fmaf(C2, p, C1 * xc);
                    const int k = kq * 4 + m;
                    ss[h] = fmaf(t, sA[k],      ss[h]);
                    sd[h] = fmaf(t, sA[16 + k], sd[h]);
                    t4[m] = t;
                }
                __half2 h0 = __floats2half2_rn(t4[0], t4[1]);
                __half2 h1 = __floats2half2_rn(t4[2], t4[3]);
                hbuf[jq * 2]     = *(uint32_t*)&h0;
                hbuf[jq * 2 + 1] = *(uint32_t*)&h1;
            }
        }
    }
    uint4* dst = (uint4*)(g_xth + (size_t)n * 64);
#pragma unroll
    for (int q = 0; q < 8; q++)
        dst[q] = make_uint4(hbuf[q*4], hbuf[q*4+1], hbuf[q*4+2], hbuf[q*4+3]);

    g_ssrc[n] = make_float4(ss[0], ss[1], ss[2], ss[3]);
    g_sdst[n] = make_float4(sd[0], sd[1], sd[2], sd[3]);
}

// ---------------------------------------------------------------------------
// Edge pass 1 (2 edges/thread): denom[col] += exp(leaky(.)); count per row,
// keeping the atomic's return as the within-row slot index. The two eidx
// values are packed into one int2 store (e0 is even -> aligned).
// (softmax-shift safely dropped: |score| <~ 17, exp within fp32 range)
// ---------------------------------------------------------------------------
__global__ void __launch_bounds__(256) kDenom(const int* __restrict__ ei, int E) {
    int t = blockIdx.x * blockDim.x + threadIdx.x;
    int e0 = t * 2;
    if (e0 >= E) return;
    bool two = (e0 + 1 < E);
    int2 rr = two ? __ldg((const int2*)(ei + e0))     : make_int2(__ldg(ei + e0), 0);
    int2 cc = two ? __ldg((const int2*)(ei + E + e0)) : make_int2(__ldg(ei + E + e0), 0);

    float4 s1a = g_ssrc[rr.x];
    float4 s2a = g_sdst[cc.x];
    float4 s1b, s2b;
    if (two) { s1b = g_ssrc[rr.y]; s2b = g_sdst[cc.y]; }

    {
        float a0 = __expf(lrelu(s1a.x + s2a.x));
        float a1 = __expf(lrelu(s1a.y + s2a.y));
        float a2 = __expf(lrelu(s1a.z + s2a.z));
        float a3 = __expf(lrelu(s1a.w + s2a.w));
        float* d = (float*)&g_denom[cc.x];
        asm volatile("red.global.add.v4.f32 [%0], {%1, %2, %3, %4};"
                     :: "l"(d), "f"(a0), "f"(a1), "f"(a2), "f"(a3) : "memory");
    }
    if (two) {
        float b0 = __expf(lrelu(s1b.x + s2b.x));
        float b1 = __expf(lrelu(s1b.y + s2b.y));
        float b2 = __expf(lrelu(s1b.z + s2b.z));
        float b3 = __expf(lrelu(s1b.w + s2b.w));
        float* d = (float*)&g_denom[cc.y];
        asm volatile("red.global.add.v4.f32 [%0], {%1, %2, %3, %4};"
                     :: "l"(d), "f"(b0), "f"(b1), "f"(b2), "f"(b3) : "memory");
        int i0 = atomicAdd(&g_cnt[rr.x], 1);
        int i1 = atomicAdd(&g_cnt[rr.y], 1);
        *(int2*)(g_eidx + e0) = make_int2(i0, i1);
    } else {
        g_eidx[e0] = atomicAdd(&g_cnt[rr.x], 1);
    }
}

// ---------------------------------------------------------------------------
// Exclusive prefix scan of counts (warp-shuffle, atomic block offset; 256/blk).
// Also packs {sdst, 0.25/(denom+eps)} into g_cd for kFill's single gather.
// ---------------------------------------------------------------------------
__global__ void __launch_bounds__(256) kScan(int n_nodes) {
    __shared__ int part[8];
    __shared__ int base;
    int tid = threadIdx.x;
    int lane = tid & 31, wid = tid >> 5;
    int i = blockIdx.x * 256 + tid;
    int v = (i < n_nodes) ? g_cnt[i] : 0;
    int s = v;
#pragma unroll
    for (int d = 1; d < 32; d <<= 1) {
        int t = __shfl_up_sync(0xffffffffu, s, d);
        if (lane >= d) s += t;
    }
    if (lane == 31) part[wid] = s;
    __syncthreads();
    if (wid == 0 && lane < 8) {
        int p = part[lane];
#pragma unroll
        for (int d = 1; d < 8; d <<= 1) {
            int t = __shfl_up_sync(0xffu, p, d);
            if (lane >= d) p += t;
        }
        part[lane] = p;
        if (lane == 7) base = atomicAdd(&g_total, p);
    }
    __syncthreads();
    if (i < n_nodes) {
        int excl = base + s - v + (wid > 0 ? part[wid - 1] : 0);
        g_start[i] = excl;
        float4 dn = g_denom[i];
        g_cd[i].sd = g_sdst[i];
        g_cd[i].di = make_float4(0.25f * __frcp_rn(dn.x + 1e-16f),
                                 0.25f * __frcp_rn(dn.y + 1e-16f),
                                 0.25f * __frcp_rn(dn.z + 1e-16f),
                                 0.25f * __frcp_rn(dn.w + 1e-16f));
    }
}

// ---------------------------------------------------------------------------
// Edge pass 2 (2 edges/thread): w once per edge; single 32B c-side gather;
// CSR slot without atomics: pos = start[r] + eidx[e] (eidx loaded as int2).
// ---------------------------------------------------------------------------
__global__ void __launch_bounds__(256) kFill(const int* __restrict__ ei, int E) {
    int t = blockIdx.x * blockDim.x + threadIdx.x;
    int e0 = t * 2;
    if (e0 >= E) return;
    bool two = (e0 + 1 < E);
    int2 rr = two ? __ldg((const int2*)(ei + e0))     : make_int2(__ldg(ei + e0), 0);
    int2 cc = two ? __ldg((const int2*)(ei + E + e0)) : make_int2(__ldg(ei + E + e0), 0);
    int2 ix = two ? *(const int2*)(g_eidx + e0)       : make_int2(g_eidx[e0], 0);

    float4 s1a = g_ssrc[rr.x];
    float4 sda = g_cd[cc.x].sd;
    float4 dia = g_cd[cc.x].di;
    float4 s1b, sdb, dib;
    if (two) { s1b = g_ssrc[rr.y]; sdb = g_cd[cc.y].sd; dib = g_cd[cc.y].di; }

    {
        float w = __expf(lrelu(s1a.x + sda.x)) * dia.x +
                  __expf(lrelu(s1a.y + sda.y)) * dia.y +
                  __expf(lrelu(s1a.z + sda.z)) * dia.z +
                  __expf(lrelu(s1a.w + sda.w)) * dia.w;
        int pos = __ldg(&g_start[rr.x]) + ix.x;
        g_cw[pos] = make_float2(__int_as_float(cc.x), w);
    }
    if (two) {
        float w = __expf(lrelu(s1b.x + sdb.x)) * dib.x +
                  __expf(lrelu(s1b.y + sdb.y)) * dib.y +
                  __expf(lrelu(s1b.z + sdb.z)) * dib.z +
                  __expf(lrelu(s1b.w + sdb.w)) * dib.w;
        int pos = __ldg(&g_start[rr.y]) + ix.y;
        g_cw[pos] = make_float2(__int_as_float(cc.y), w);
    }
}

// ---------------------------------------------------------------------------
// Pull: one warp per row, lane owns 2 features (half2 gather, fp32 accum).
// x4 unroll with independent accumulators (verified best); cw metadata now
// loaded as lane-uniform float4 pairs (2 edges per LDG), with a 1-edge peel
// to make the float4 pointer 16B-aligned. Gather pattern unchanged.
// ---------------------------------------------------------------------------
__global__ void __launch_bounds__(256) kPull(float* __restrict__ out, int n_nodes) {
    int row = blockIdx.x * (blockDim.x >> 5) + (threadIdx.x >> 5);
    if (row >= n_nodes) return;
    int lane = threadIdx.x & 31;
    int start = g_start[row];
    int cnt   = g_cnt[row];

    const __half2* __restrict__ xt2 = (const __half2*)g_xth;
    float ax = 0.f, ay = 0.f, bx = 0.f, by = 0.f;

    int j = 0;
    if ((start & 1) && cnt > 0) {   // peel to align (start+j) to even
        float2 cw = __ldg(&g_cw[start]);
        __half2 xv = __ldg(&xt2[(size_t)__float_as_int(cw.x) * 32 + lane]);
        float2 f = __half22float2(xv);
        ax = fmaf(cw.y, f.x, ax); ay = fmaf(cw.y, f.y, ay);
        j = 1;
    }
    const float4* cw4 = (const float4*)(g_cw + start + j);   // 16B aligned
    for (; j + 4 <= cnt; j += 4, cw4 += 2) {
        float4 p0 = __ldg(cw4);       // {col0, w0, col1, w1}
        float4 p1 = __ldg(cw4 + 1);   // {col2, w2, col3, w3}
        __half2 x0 = __ldg(&xt2[(size_t)__float_as_int(p0.x) * 32 + lane]);
        __half2 x1 = __ldg(&xt2[(size_t)__float_as_int(p0.z) * 32 + lane]);
        __half2 x2 = __ldg(&xt2[(size_t)__float_as_int(p1.x) * 32 + lane]);
        __half2 x3 = __ldg(&xt2[(size_t)__float_as_int(p1.z) * 32 + lane]);
        float2 f0 = __half22float2(x0);
        float2 f1 = __half22float2(x1);
        float2 f2 = __half22float2(x2);
        float2 f3 = __half22float2(x3);
        ax = fmaf(p0.y, f0.x, ax); ay = fmaf(p0.y, f0.y, ay);
        bx = fmaf(p0.w, f1.x, bx); by = fmaf(p0.w, f1.y, by);
        ax = fmaf(p1.y, f2.x, ax); ay = fmaf(p1.y, f2.y, ay);
        bx = fmaf(p1.w, f3.x, bx); by = fmaf(p1.w, f3.y, by);
    }
    for (; j < cnt; j++) {
        float2 cw = __ldg(&g_cw[start + j]);
        __half2 xv = __ldg(&xt2[(size_t)__float_as_int(cw.x) * 32 + lane]);
        float2 f = __half22float2(xv);
        ax = fmaf(cw.y, f.x, ax); ay = fmaf(cw.y, f.y, ay);
    }
    ((float2*)out)[(size_t)row * 32 + lane] = make_float2(ax + bx, ay + by);
}

// ---------------------------------------------------------------------------
// inputs: x[N*64] f32, edge_index[2*E] i32, edge_weight[E] f32 (unused),
//         W[64*64] f32, a[32] f32   |  output: out[N*64] f32
// ---------------------------------------------------------------------------
extern "C" void kernel_launch(void* const* d_in, const int* in_sizes, int n_in,
                              void* d_out, int out_size) {
    const float* x  = (const float*)d_in[0];
    const int*   ei = (const int*)d_in[1];
    const float* W  = (const float*)d_in[3];
    const float* a  = (const float*)d_in[4];
    float* out = (float*)d_out;

    int N = in_sizes[0] / 64;
    int E = in_sizes[2];
    int halfE = (E + 1) / 2;

    kZero<<<(N + 255) / 256, 256>>>(W, N);
    kNode<<<(N + 255) / 256, 256>>>(x, W, a, N);
    kDenom<<<(halfE + 255) / 256, 256>>>(ei, E);
    kScan<<<(N + 255) / 256, 256>>>(N);
    kFill<<<(halfE + 255) / 256, 256>>>(ei, E);
    kPull<<<(N + 7) / 8, 256>>>(out, N);
}

// round 17
// speedup vs baseline: 1.0968x; 1.0182x over previous
#include <cuda_runtime.h>
#include <cuda_fp16.h>
#include <cstdint>

// Problem constants: N=100000, D=64, H=4, DK=16, E=1600000
#define MAXN 100000
#define MAXE 1600000

// xt = C1*x + C2*(x @ W^T)  where M^4, M=[[1,.25],[-.25,1]] (exact binary fracs)
#define C1 0.62890625f
#define C2 0.9375f
#define KI 1.56640625f   // C1 + C2 (exact), used when W == I
#define ALPHA 0.2f

// Scratch (static device arrays — no allocation allowed)
__device__ __half g_xth[MAXN * 64];   // transformed features, fp16 (12.8 MB)
__device__ float4 g_ssrc[MAXN];       // per-node per-head src score
__device__ float4 g_sdst[MAXN];       // per-node per-head dst score
__device__ float4 g_denom[MAXN];      // softmax denominator accumulators
__device__ float4 g_di[MAXN];         // 0.25/(denom+eps)
__device__ int    g_cnt[MAXN];        // out-degree by row
__device__ int    g_start[MAXN];      // CSR row start
__device__ int    g_total;            // scan running offset
__device__ int    g_wflag;            // 0 iff W == identity
__device__ int    g_eidx[MAXE];       // within-row occurrence index (from kDenom)
__device__ float4 g_e4[MAXE];         // per-edge exps staged by kDenom
__device__ float2 g_cw[MAXE];         // per-edge (col, w)

__device__ __forceinline__ float lrelu(float v) {
    return v > 0.0f ? v : ALPHA * v;
}

// ---------------------------------------------------------------------------
// Zero per-replay state; also verify W == identity (first 4096 threads)
// ---------------------------------------------------------------------------
__global__ void kZero(const float* __restrict__ W, int n_nodes) {
    int i = blockIdx.x * blockDim.x + threadIdx.x;
    if (i == 0) { g_total = 0; g_wflag = 0; }
    if (i < 4096) {
        float expect = (i / 64 == i % 64) ? 1.0f : 0.0f;
        unsigned bad = __ballot_sync(0xffffffffu, W[i] != expect);
        if ((threadIdx.x & 31) == 0 && bad) atomicOr(&g_wflag, 1);
    }
    if (i < n_nodes) {
        g_denom[i] = make_float4(0.f, 0.f, 0.f, 0.f);
        g_cnt[i] = 0;
    }
}

// ---------------------------------------------------------------------------
// Per-node: xt = C1*x + C2*(x@W^T) (stored fp16); per-head scores (fp32).
// Fast path (W==I): xt = KI*x, pure streaming.
// ---------------------------------------------------------------------------
__global__ void __launch_bounds__(256) kNode(
    const float* __restrict__ x, const float* __restrict__ W,
    const float* __restrict__ a, int n_nodes)
{
    __shared__ float4 sW[1024];
    __shared__ float  sA[32];
    const bool ident = (g_wflag == 0);
    if (!ident) {
        for (int k = threadIdx.x; k < 1024; k += blockDim.x)
            sW[k] = ((const float4*)W)[k];
    }
    if (threadIdx.x < 32) sA[threadIdx.x] = a[threadIdx.x];
    __syncthreads();

    int n = blockIdx.x * blockDim.x + threadIdx.x;
    if (n >= n_nodes) return;

    float4 xr[16];
    const float4* xv = (const float4*)(x + (size_t)n * 64);
#pragma unroll
    for (int i = 0; i < 16; i++) xr[i] = xv[i];

    float ss[4] = {0.f, 0.f, 0.f, 0.f};
    float sd[4] = {0.f, 0.f, 0.f, 0.f};
    uint32_t hbuf[32];   // 64 halfs as 32 half2 words

    if (ident) {
#pragma unroll
        for (int jq = 0; jq < 16; jq++) {
            const int h = jq >> 2;
            float4 xq = xr[jq];
            float t0 = KI * xq.x, t1 = KI * xq.y, t2 = KI * xq.z, t3 = KI * xq.w;
            const int k = (jq & 3) * 4;
            ss[h] = fmaf(t0, sA[k],     fmaf(t1, sA[k+1],    fmaf(t2, sA[k+2],    fmaf(t3, sA[k+3],    ss[h]))));
            sd[h] = fmaf(t0, sA[16+k],  fmaf(t1, sA[16+k+1], fmaf(t2, sA[16+k+2], fmaf(t3, sA[16+k+3], sd[h]))));
            __half2 h0 = __floats2half2_rn(t0, t1);
            __half2 h1 = __floats2half2_rn(t2, t3);
            hbuf[jq * 2]     = *(uint32_t*)&h0;
            hbuf[jq * 2 + 1] = *(uint32_t*)&h1;
        }
    } else {
#pragma unroll
        for (int h = 0; h < 4; h++) {
#pragma unroll
            for (int kq = 0; kq < 4; kq++) {
                const int jq = h * 4 + kq;
                float4 xq = xr[jq];
                float t4[4];
#pragma unroll
                for (int m = 0; m < 4; m++) {
                    const int j = jq * 4 + m;
                    const float4* wr = &sW[j * 16];
                    float p = 0.f;
#pragma unroll
                    for (int i = 0; i < 16; i++) {
                        float4 w  = wr[i];
                        float4 xx = xr[i];
                        p = fmaf(xx.x, w.x, p);
                        p = fmaf(xx.y, w.y, p);
                        p = fmaf(xx.z, w.z, p);
                        p = fmaf(xx.w, w.w, p);
                    }
                    float xc = (m == 0) ? xq.x : (m == 1) ? xq.y : (m == 2) ? xq.z : xq.w;
                    float t  = fmaf(C2, p, C1 * xc);
                    const int k = kq * 4 + m;
                    ss[h] = fmaf(t, sA[k],      ss[h]);
                    sd[h] = fmaf(t, sA[16 + k], sd[h]);
                    t4[m] = t;
                }
                __half2 h0 = __floats2half2_rn(t4[0], t4[1]);
                __half2 h1 = __floats2half2_rn(t4[2], t4[3]);
                hbuf[jq * 2]     = *(uint32_t*)&h0;
                hbuf[jq * 2 + 1] = *(uint32_t*)&h1;
            }
        }
    }
    uint4* dst = (uint4*)(g_xth + (size_t)n * 64);
#pragma unroll
    for (int q = 0; q < 8; q++)
        dst[q] = make_uint4(hbuf[q*4], hbuf[q*4+1], hbuf[q*4+2], hbuf[q*4+3]);

    g_ssrc[n] = make_float4(ss[0], ss[1], ss[2], ss[3]);
    g_sdst[n] = make_float4(sd[0], sd[1], sd[2], sd[3]);
}

// ---------------------------------------------------------------------------
// Edge pass 1 (2 edges/thread): denom[col] += exps; count per row (atomic
// return = within-row slot index, packed int2 store); stage exps in g_e4 so
// kFill never re-gathers scores or re-runs expf.
// (softmax-shift safely dropped: |score| <~ 17, exp within fp32 range)
// ---------------------------------------------------------------------------
__global__ void __launch_bounds__(256) kDenom(const int* __restrict__ ei, int E) {
    int t = blockIdx.x * blockDim.x + threadIdx.x;
    int e0 = t * 2;
    if (e0 >= E) return;
    bool two = (e0 + 1 < E);
    int2 rr = two ? __ldg((const int2*)(ei + e0))     : make_int2(__ldg(ei + e0), 0);
    int2 cc = two ? __ldg((const int2*)(ei + E + e0)) : make_int2(__ldg(ei + E + e0), 0);

    float4 s1a = g_ssrc[rr.x];
    float4 s2a = g_sdst[cc.x];
    float4 s1b, s2b;
    if (two) { s1b = g_ssrc[rr.y]; s2b = g_sdst[cc.y]; }

    {
        float a0 = __expf(lrelu(s1a.x + s2a.x));
        float a1 = __expf(lrelu(s1a.y + s2a.y));
        float a2 = __expf(lrelu(s1a.z + s2a.z));
        float a3 = __expf(lrelu(s1a.w + s2a.w));
        float* d = (float*)&g_denom[cc.x];
        asm volatile("red.global.add.v4.f32 [%0], {%1, %2, %3, %4};"
                     :: "l"(d), "f"(a0), "f"(a1), "f"(a2), "f"(a3) : "memory");
        g_e4[e0] = make_float4(a0, a1, a2, a3);
    }
    if (two) {
        float b0 = __expf(lrelu(s1b.x + s2b.x));
        float b1 = __expf(lrelu(s1b.y + s2b.y));
        float b2 = __expf(lrelu(s1b.z + s2b.z));
        float b3 = __expf(lrelu(s1b.w + s2b.w));
        float* d = (float*)&g_denom[cc.y];
        asm volatile("red.global.add.v4.f32 [%0], {%1, %2, %3, %4};"
                     :: "l"(d), "f"(b0), "f"(b1), "f"(b2), "f"(b3) : "memory");
        g_e4[e0 + 1] = make_float4(b0, b1, b2, b3);
        int i0 = atomicAdd(&g_cnt[rr.x], 1);
        int i1 = atomicAdd(&g_cnt[rr.y], 1);
        *(int2*)(g_eidx + e0) = make_int2(i0, i1);
    } else {
        g_eidx[e0] = atomicAdd(&g_cnt[rr.x], 1);
    }
}

// ---------------------------------------------------------------------------
// Exclusive prefix scan of counts (warp-shuffle, atomic block offset; 256/blk).
// Also inverts denominators (1/H mean folded in).
// ---------------------------------------------------------------------------
__global__ void __launch_bounds__(256) kScan(int n_nodes) {
    __shared__ int part[8];
    __shared__ int base;
    int tid = threadIdx.x;
    int lane = tid & 31, wid = tid >> 5;
    int i = blockIdx.x * 256 + tid;
    int v = (i < n_nodes) ? g_cnt[i] : 0;
    int s = v;
#pragma unroll
    for (int d = 1; d < 32; d <<= 1) {
        int t = __shfl_up_sync(0xffffffffu, s, d);
        if (lane >= d) s += t;
    }
    if (lane == 31) part[wid] = s;
    __syncthreads();
    if (wid == 0 && lane < 8) {
        int p = part[lane];
#pragma unroll
        for (int d = 1; d < 8; d <<= 1) {
            int t = __shfl_up_sync(0xffu, p, d);
            if (lane >= d) p += t;
        }
        part[lane] = p;
        if (lane == 7) base = atomicAdd(&g_total, p);
    }
    __syncthreads();
    if (i < n_nodes) {
        int excl = base + s - v + (wid > 0 ? part[wid - 1] : 0);
        g_start[i] = excl;
        float4 dn = g_denom[i];
        g_di[i] = make_float4(0.25f * __frcp_rn(dn.x + 1e-16f),
                              0.25f * __frcp_rn(dn.y + 1e-16f),
                              0.25f * __frcp_rn(dn.z + 1e-16f),
                              0.25f * __frcp_rn(dn.w + 1e-16f));
    }
}

// ---------------------------------------------------------------------------
// Edge pass 2 (2 edges/thread): w = staged e4 · di[c]. ONE random sector
// per edge (di), zero MUFU, CSR slot without atomics (start[r] + eidx).
// ---------------------------------------------------------------------------
__global__ void __launch_bounds__(256) kFill(const int* __restrict__ ei, int E) {
    int t = blockIdx.x * blockDim.x + threadIdx.x;
    int e0 = t * 2;
    if (e0 >= E) return;
    bool two = (e0 + 1 < E);
    int2 rr = two ? __ldg((const int2*)(ei + e0))     : make_int2(__ldg(ei + e0), 0);
    int2 cc = two ? __ldg((const int2*)(ei + E + e0)) : make_int2(__ldg(ei + E + e0), 0);
    int2 ix = two ? *(const int2*)(g_eidx + e0)       : make_int2(g_eidx[e0], 0);

    float4 ea  = g_e4[e0];
    float4 dia = __ldg(&g_di[cc.x]);
    float4 eb, dib;
    if (two) { eb = g_e4[e0 + 1]; dib = __ldg(&g_di[cc.y]); }

    {
        float w = ea.x * dia.x + ea.y * dia.y + ea.z * dia.z + ea.w * dia.w;
        int pos = __ldg(&g_start[rr.x]) + ix.x;
        g_cw[pos] = make_float2(__int_as_float(cc.x), w);
    }
    if (two) {
        float w = eb.x * dib.x + eb.y * dib.y + eb.z * dib.z + eb.w * dib.w;
        int pos = __ldg(&g_start[rr.y]) + ix.y;
        g_cw[pos] = make_float2(__int_as_float(cc.y), w);
    }
}

// ---------------------------------------------------------------------------
// Pull: one warp per row, lane owns 2 features (half2 gather, fp32 accum).
// x4 unroll, float4-packed cw loads with 1-edge alignment peel.
// (FROZEN — identical to the 114.8us version.)
// ---------------------------------------------------------------------------
__global__ void __launch_bounds__(256) kPull(float* __restrict__ out, int n_nodes) {
    int row = blockIdx.x * (blockDim.x >> 5) + (threadIdx.x >> 5);
    if (row >= n_nodes) return;
    int lane = threadIdx.x & 31;
    int start = g_start[row];
    int cnt   = g_cnt[row];

    const __half2* __restrict__ xt2 = (const __half2*)g_xth;
    float ax = 0.f, ay = 0.f, bx = 0.f, by = 0.f;

    int j = 0;
    if ((start & 1) && cnt > 0) {   // peel to align (start+j) to even
        float2 cw = __ldg(&g_cw[start]);
        __half2 xv = __ldg(&xt2[(size_t)__float_as_int(cw.x) * 32 + lane]);
        float2 f = __half22float2(xv);
        ax = fmaf(cw.y, f.x, ax); ay = fmaf(cw.y, f.y, ay);
        j = 1;
    }
    const float4* cw4 = (const float4*)(g_cw + start + j);   // 16B aligned
    for (; j + 4 <= cnt; j += 4, cw4 += 2) {
        float4 p0 = __ldg(cw4);       // {col0, w0, col1, w1}
        float4 p1 = __ldg(cw4 + 1);   // {col2, w2, col3, w3}
        __half2 x0 = __ldg(&xt2[(size_t)__float_as_int(p0.x) * 32 + lane]);
        __half2 x1 = __ldg(&xt2[(size_t)__float_as_int(p0.z) * 32 + lane]);
        __half2 x2 = __ldg(&xt2[(size_t)__float_as_int(p1.x) * 32 + lane]);
        __half2 x3 = __ldg(&xt2[(size_t)__float_as_int(p1.z) * 32 + lane]);
        float2 f0 = __half22float2(x0);
        float2 f1 = __half22float2(x1);
        float2 f2 = __half22float2(x2);
        float2 f3 = __half22float2(x3);
        ax = fmaf(p0.y, f0.x, ax); ay = fmaf(p0.y, f0.y, ay);
        bx = fmaf(p0.w, f1.x, bx); by = fmaf(p0.w, f1.y, by);
        ax = fmaf(p1.y, f2.x, ax); ay = fmaf(p1.y, f2.y, ay);
        bx = fmaf(p1.w, f3.x, bx); by = fmaf(p1.w, f3.y, by);
    }
    for (; j < cnt; j++) {
        float2 cw = __ldg(&g_cw[start + j]);
        __half2 xv = __ldg(&xt2[(size_t)__float_as_int(cw.x) * 32 + lane]);
        float2 f = __half22float2(xv);
        ax = fmaf(cw.y, f.x, ax); ay = fmaf(cw.y, f.y, ay);
    }
    ((float2*)out)[(size_t)row * 32 + lane] = make_float2(ax + bx, ay + by);
}

// ---------------------------------------------------------------------------
// inputs: x[N*64] f32, edge_index[2*E] i32, edge_weight[E] f32 (unused),
//         W[64*64] f32, a[32] f32   |  output: out[N*64] f32
// ---------------------------------------------------------------------------
extern "C" void kernel_launch(void* const* d_in, const int* in_sizes, int n_in,
                              void* d_out, int out_size) {
    const float* x  = (const float*)d_in[0];
    const int*   ei = (const int*)d_in[1];
    const float* W  = (const float*)d_in[3];
    const float* a  = (const float*)d_in[4];
    float* out = (float*)d_out;

    int N = in_sizes[0] / 64;
    int E = in_sizes[2];
    int halfE = (E + 1) / 2;

    kZero<<<(N + 255) / 256, 256>>>(W, N);
    kNode<<<(N + 255) / 256, 256>>>(x, W, a, N);
    kDenom<<<(halfE + 255) / 256, 256>>>(ei, E);
    kScan<<<(N + 255) / 256, 256>>>(N);
    kFill<<<(halfE + 255) / 256, 256>>>(ei, E);
    kPull<<<(N + 7) / 8, 256>>>(out, N);
}